// round 4
// baseline (speedup 1.0000x reference)
#include <cuda_runtime.h>

#define GRID 256
#define BB   4
#define NN   256
#define OBSD 40
#define TT   256
#define DIMG 32
#define HEADG 8
#define ACTD 8

// Scratch
__device__ float g_H1[BB * NN * TT];
__device__ float g_EMBp[4][BB * NN * TT];
__device__ float g_EMB[BB * NN * TT];
__device__ float g_NEp[4][BB * NN * TT];
__device__ float g_NE[BB * NN * TT];
__device__ float g_sumNH[BB * TT];
__device__ float g_sumHID[BB * TT];
__device__ unsigned g_bar[8];

// ---------------------------------------------------------------------------
__global__ void reset_kernel() {
    int t = threadIdx.x;
    if (t < 8) g_bar[t] = 0u;
    for (int i = t; i < BB * TT; i += 256) {
        g_sumNH[i] = 0.f;
        g_sumHID[i] = 0.f;
    }
}

// ---------------------------------------------------------------------------
__device__ __forceinline__ unsigned ld_volatile_u32(const unsigned* p) {
    unsigned v;
    asm volatile("ld.volatile.global.u32 %0, [%1];" : "=r"(v) : "l"(p));
    return v;
}

__device__ __forceinline__ void gbar(int k) {
    __syncthreads();
    if (threadIdx.x == 0) {
        __threadfence();
        unsigned prev = atomicAdd(&g_bar[k], 1u);
        if (prev + 1u < (unsigned)GRID) {
            while (ld_volatile_u32(&g_bar[k]) < (unsigned)GRID) __nanosleep(32);
        }
        __threadfence();
    }
    __syncthreads();
}

// ---------------------------------------------------------------------------
// 64x64 tile, K=64 (4 k-tiles of 16), double-buffered, 4x4 microtile.
// ---------------------------------------------------------------------------
__device__ __forceinline__ void gemm64x64k64(const float* __restrict__ A, int lda,
                                             const float* __restrict__ B, int ldb,
                                             float acc[4][4], int tid,
                                             float As[2][16][68], float Bs[2][16][68])
{
    const int ty = tid >> 4, tx = tid & 15;
#pragma unroll
    for (int i = 0; i < 4; ++i) {
        int idx = tid + i * 256;
        int r = idx >> 4, k = idx & 15;
        As[0][k][r] = A[r * lda + k];
        int c = idx & 63, kk = idx >> 6;
        Bs[0][kk][c] = B[kk * ldb + c];
    }
    __syncthreads();
#pragma unroll
    for (int t = 0; t < 4; ++t) {
        float ra[4], rb[4];
        if (t < 3) {
            int k0 = (t + 1) * 16;
#pragma unroll
            for (int i = 0; i < 4; ++i) {
                int idx = tid + i * 256;
                int r = idx >> 4, k = idx & 15;
                ra[i] = A[r * lda + k0 + k];
                int c = idx & 63, kk = idx >> 6;
                rb[i] = B[(k0 + kk) * ldb + c];
            }
        }
        int buf = t & 1;
#pragma unroll
        for (int k = 0; k < 16; ++k) {
            float a[4], b[4];
            *(float4*)a = *(const float4*)&As[buf][k][ty * 4];
            *(float4*)b = *(const float4*)&Bs[buf][k][tx * 4];
#pragma unroll
            for (int i = 0; i < 4; ++i)
#pragma unroll
                for (int j = 0; j < 4; ++j) acc[i][j] = fmaf(a[i], b[j], acc[i][j]);
        }
        if (t < 3) {
            int nb = buf ^ 1;
#pragma unroll
            for (int i = 0; i < 4; ++i) {
                int idx = tid + i * 256;
                int r = idx >> 4, k = idx & 15;
                As[nb][k][r] = ra[i];
                int c = idx & 63, kk = idx >> 6;
                Bs[nb][kk][c] = rb[i];
            }
            __syncthreads();
        }
    }
}

// ---------------------------------------------------------------------------
__global__ void __launch_bounds__(256, 2)
fused_kernel(const float* __restrict__ x, const float* __restrict__ adj,
             const float* __restrict__ We1, const float* __restrict__ be1,
             const float* __restrict__ We2, const float* __restrict__ be2,
             const float* __restrict__ Wl, const float* __restrict__ bl,
             const float* __restrict__ Wn, const float* __restrict__ bn,
             const float* __restrict__ Wh, const float* __restrict__ bh,
             const float* __restrict__ Wa, const float* __restrict__ ba,
             float* __restrict__ out)
{
    __shared__ float As[2][16][68];
    __shared__ float Bs[2][16][68];

    const int bid = blockIdx.x;
    const int tid = threadIdx.x;
    const int ty = tid >> 4, tx = tid & 15;

    // ================= P0: H1 = relu(obs @ We1 + be1), bids 0..63 ==========
    if (bid < 64) {
        const int r0 = (bid >> 2) * 64;
        const int c0 = (bid & 3) * 64;
        float acc[4][4] = {};
        for (int k0 = 0; k0 < 48; k0 += 16) {
#pragma unroll
            for (int i = 0; i < 4; ++i) {
                int idx = tid + i * 256;
                int r = idx >> 4, k = idx & 15;
                int row = r0 + r, b = row >> 8, n = row & 255;
                As[0][k][r] = (k0 + k < OBSD) ? x[b * ((NN + 1) * OBSD) + n * OBSD + k0 + k] : 0.f;
                int c = idx & 63, kk = idx >> 6;
                Bs[0][kk][c] = (k0 + kk < OBSD) ? We1[(k0 + kk) * TT + c0 + c] : 0.f;
            }
            __syncthreads();
#pragma unroll
            for (int k = 0; k < 16; ++k) {
                float a[4], b[4];
                *(float4*)a = *(const float4*)&As[0][k][ty * 4];
                *(float4*)b = *(const float4*)&Bs[0][k][tx * 4];
#pragma unroll
                for (int i = 0; i < 4; ++i)
#pragma unroll
                    for (int j = 0; j < 4; ++j) acc[i][j] = fmaf(a[i], b[j], acc[i][j]);
            }
            __syncthreads();
        }
#pragma unroll
        for (int i = 0; i < 4; ++i)
#pragma unroll
            for (int j = 0; j < 4; ++j) {
                int c = c0 + tx * 4 + j;
                g_H1[(r0 + ty * 4 + i) * TT + c] = fmaxf(acc[i][j] + be1[c], 0.f);
            }
    }
    gbar(0);

    // ================= P1: EMBp[s] = H1 @ We2 (split-K x4) =================
    {
        const int s = bid >> 6;
        const int t = bid & 63;
        const int r0 = (t >> 2) * 64;
        const int c0 = (t & 3) * 64;
        float acc[4][4] = {};
        gemm64x64k64(g_H1 + r0 * TT + s * 64, TT,
                     We2 + (s * 64) * TT + c0, TT, acc, tid, As, Bs);
        float* C = &g_EMBp[s][r0 * TT + c0];
#pragma unroll
        for (int i = 0; i < 4; ++i)
#pragma unroll
            for (int j = 0; j < 4; ++j)
                C[(ty * 4 + i) * TT + tx * 4 + j] = acc[i][j];
    }
    gbar(1);

    // ================= P1.5: EMB = relu(sum partials + be2) ================
    {
        int g = bid * 1024 + tid * 4;
        int c = g & 255;
        float4 p0 = *(const float4*)&g_EMBp[0][g];
        float4 p1 = *(const float4*)&g_EMBp[1][g];
        float4 p2 = *(const float4*)&g_EMBp[2][g];
        float4 p3 = *(const float4*)&g_EMBp[3][g];
        float4 r;
        r.x = fmaxf(p0.x + p1.x + p2.x + p3.x + be2[c + 0], 0.f);
        r.y = fmaxf(p0.y + p1.y + p2.y + p3.y + be2[c + 1], 0.f);
        r.z = fmaxf(p0.z + p1.z + p2.z + p3.z + be2[c + 2], 0.f);
        r.w = fmaxf(p0.w + p1.w + p2.w + p3.w + be2[c + 3], 0.f);
        *(float4*)&g_EMB[g] = r;
    }
    gbar(2);

    // ================= P2: NEp[s][b] = adj @ EMB[b] (split-K x4) ===========
    {
        const int s = bid >> 6;
        const int t = bid & 63;
        const int b = t >> 4;
        const int r0 = ((t >> 2) & 3) * 64;
        const int c0 = (t & 3) * 64;
        float acc[4][4] = {};
        gemm64x64k64(adj + r0 * NN + s * 64, NN,
                     g_EMB + b * (NN * TT) + (s * 64) * TT + c0, TT, acc, tid, As, Bs);
        float* C = &g_NEp[s][b * (NN * TT) + r0 * TT + c0];
#pragma unroll
        for (int i = 0; i < 4; ++i)
#pragma unroll
            for (int j = 0; j < 4; ++j)
                C[(ty * 4 + i) * TT + tx * 4 + j] = acc[i][j];
    }
    gbar(3);

    // ================= P2.5: NE = sum partials =============================
    {
        int g = bid * 1024 + tid * 4;
        float4 p0 = *(const float4*)&g_NEp[0][g];
        float4 p1 = *(const float4*)&g_NEp[1][g];
        float4 p2 = *(const float4*)&g_NEp[2][g];
        float4 p3 = *(const float4*)&g_NEp[3][g];
        float4 r;
        r.x = p0.x + p1.x + p2.x + p3.x;
        r.y = p0.y + p1.y + p2.y + p3.y;
        r.z = p0.z + p1.z + p2.z + p3.z;
        r.w = p0.w + p1.w + p2.w + p3.w;
        *(float4*)&g_NE[g] = r;
    }
    gbar(4);

    // ================= P3: colsum(relu(NE @ {Wn,Wh} + bias)) ===============
    {
        const int rc = bid & 7;            // 8 row chunks of 32
        const int rest = bid >> 3;
        const int ct = rest & 3;           // 4 col tiles of 64
        const int w = (rest >> 2) & 1;     // weight select
        const int b = rest >> 3;           // batch
        const int r0 = rc * 32;
        const int c0 = ct * 64;
        const float* A = g_NE + b * (NN * TT) + r0 * TT;
        const float* W = (w ? Wh : Wn) + c0;

        float acc[2][4] = {};
#pragma unroll
        for (int i = 0; i < 2; ++i) {
            int idx = tid + i * 256;
            int r = idx & 31, k = idx >> 5;
            As[0][k][r] = A[r * TT + k];
        }
#pragma unroll
        for (int i = 0; i < 4; ++i) {
            int idx = tid + i * 256;
            int c = idx & 63, kk = idx >> 6;
            Bs[0][kk][c] = W[kk * TT + c];
        }
        __syncthreads();
        for (int t = 0; t < 16; ++t) {
            float ra[2], rb[4];
            if (t < 15) {
                int k0 = (t + 1) * 16;
#pragma unroll
                for (int i = 0; i < 2; ++i) {
                    int idx = tid + i * 256;
                    int r = idx & 31, k = idx >> 5;
                    ra[i] = A[r * TT + k0 + k];
                }
#pragma unroll
                for (int i = 0; i < 4; ++i) {
                    int idx = tid + i * 256;
                    int c = idx & 63, kk = idx >> 6;
                    rb[i] = W[(k0 + kk) * TT + c];
                }
            }
            int buf = t & 1;
#pragma unroll
            for (int k = 0; k < 16; ++k) {
                float a[2], bv[4];
                *(float2*)a = *(const float2*)&As[buf][k][ty * 2];
                *(float4*)bv = *(const float4*)&Bs[buf][k][tx * 4];
#pragma unroll
                for (int i = 0; i < 2; ++i)
#pragma unroll
                    for (int j = 0; j < 4; ++j) acc[i][j] = fmaf(a[i], bv[j], acc[i][j]);
            }
            if (t < 15) {
                int nb = buf ^ 1;
#pragma unroll
                for (int i = 0; i < 2; ++i) {
                    int idx = tid + i * 256;
                    int r = idx & 31, k = idx >> 5;
                    As[nb][k][r] = ra[i];
                }
#pragma unroll
                for (int i = 0; i < 4; ++i) {
                    int idx = tid + i * 256;
                    int c = idx & 63, kk = idx >> 6;
                    Bs[nb][kk][c] = rb[i];
                }
                __syncthreads();
            }
        }
        const float* bi = (w ? bh : bn);
        float* dst = (w ? g_sumHID : g_sumNH);
        float* red = &As[0][0][0];   // 1024 floats
        __syncthreads();
#pragma unroll
        for (int j = 0; j < 4; ++j) {
            int col = tx * 4 + j;
            float bv = bi[c0 + col];
            red[ty * 64 + col] = fmaxf(acc[0][j] + bv, 0.f) + fmaxf(acc[1][j] + bv, 0.f);
        }
        __syncthreads();
        if (tid < 64) {
            float s = 0.f;
#pragma unroll
            for (int t2 = 0; t2 < 16; ++t2) s += red[t2 * 64 + tid];
            atomicAdd(&dst[b * TT + c0 + tid], s);
        }
    }
    gbar(5);

    // ================= P4: epilogue, bids 0..3 =============================
    if (bid < 4) {
        float* sp = &As[0][0][0];
        float* er = sp;           // 256
        float* av = sp + 256;     // 256
        float* prod = sp + 512;   // 256
        float* mx = sp + 768;     // 8
        float* sm = sp + 776;     // 8
        float* od = sp + 784;     // 32

        const int b = bid;
        const int t = tid;
        const int tgt = (int)x[b * ((NN + 1) * OBSD) + NN * OBSD];
        er[t] = g_EMB[(b * NN + tgt) * TT + t];
        __syncthreads();

        float acc = bl[t];
#pragma unroll 8
        for (int k = 0; k < TT; ++k) acc = fmaf(er[k], Wl[k * TT + t], acc);
        float l = fmaxf(acc, 0.f);
        av[t] = l * g_sumNH[b * TT + t];
        __syncthreads();

        if (t < HEADG) {
            float m = -1e30f;
            for (int d = 0; d < DIMG; ++d) m = fmaxf(m, av[d * HEADG + t]);
            float s = 0.f;
            for (int d = 0; d < DIMG; ++d) s += __expf(av[d * HEADG + t] - m);
            mx[t] = m; sm[t] = s;
        }
        __syncthreads();

        int h = t & (HEADG - 1);
        float attn = __expf(av[t] - mx[h]) / sm[h];
        prod[t] = attn * g_sumHID[b * TT + t];
        __syncthreads();

        if (t < DIMG) {
            float s = 0.f;
#pragma unroll
            for (int hh = 0; hh < HEADG; ++hh) s += prod[t * HEADG + hh];
            od[t] = s * (1.0f / HEADG);
        }
        __syncthreads();

        if (t < ACTD) {
            float a = ba[t];
#pragma unroll
            for (int d = 0; d < DIMG; ++d) a = fmaf(od[d], Wa[d * ACTD + t], a);
            out[b * ACTD + t] = a;
        }
    }
}

// ---------------------------------------------------------------------------
extern "C" void kernel_launch(void* const* d_in, const int* in_sizes, int n_in,
                              void* d_out, int out_size)
{
    const float* x   = (const float*)d_in[0];
    const float* adj = (const float*)d_in[1];
    const float* We1 = (const float*)d_in[2];
    const float* be1 = (const float*)d_in[3];
    const float* We2 = (const float*)d_in[4];
    const float* be2 = (const float*)d_in[5];
    const float* Wl  = (const float*)d_in[6];
    const float* bl  = (const float*)d_in[7];
    const float* Wn  = (const float*)d_in[8];
    const float* bn  = (const float*)d_in[9];
    const float* Wh  = (const float*)d_in[10];
    const float* bh  = (const float*)d_in[11];
    const float* Wa  = (const float*)d_in[12];
    const float* ba  = (const float*)d_in[13];
    float* out = (float*)d_out;

    reset_kernel<<<1, 256>>>();
    fused_kernel<<<GRID, 256>>>(x, adj, We1, be1, We2, be2, Wl, bl,
                                Wn, bn, Wh, bh, Wa, ba, out);
}

// round 5
// speedup vs baseline: 1.6941x; 1.6941x over previous
#include <cuda_runtime.h>

#define BB   4
#define NN   256
#define OBSD 40
#define TT   256
#define DIMG 32
#define HEADG 8
#define ACTD 8

__device__ float g_H1[BB * NN * TT];
__device__ float g_EMBp[2][BB * NN * TT];
__device__ float g_NEp[2][BB * NN * TT];
__device__ float g_sumNH[BB * TT];
__device__ float g_sumHID[BB * TT];

// ---------------------------------------------------------------------------
// 32x64 output tile, 256 threads, 2x4 micro-tile, double-buffered k-tiles of 16.
// ldA(kt, r, k)  -> A element for row r (0..31), k (0..15) of k-tile kt
// ldB(kt, kk, c) -> B element for k kk (0..15), col c (0..63) of k-tile kt
// ---------------------------------------------------------------------------
template <class FA, class FB>
__device__ __forceinline__ void mm32x64(FA ldA, FB ldB, int nkt,
                                        float acc[2][4], int tid,
                                        float As[2][16][33], float Bs[2][16][68])
{
    const int ty = tid >> 4, tx = tid & 15;
    {
        int r = tid >> 4, k = tid & 15;           // covers 256 of 512
        As[0][k][r] = ldA(0, r, k);
        As[0][k][r + 16] = ldA(0, r + 16, k);
#pragma unroll
        for (int i = 0; i < 4; ++i) {
            int idx = tid + i * 256;
            Bs[0][idx >> 6][idx & 63] = ldB(0, idx >> 6, idx & 63);
        }
    }
    __syncthreads();
    for (int t = 0; t < nkt; ++t) {
        float ra0, ra1, rb[4];
        if (t + 1 < nkt) {
            int r = tid >> 4, k = tid & 15;
            ra0 = ldA(t + 1, r, k);
            ra1 = ldA(t + 1, r + 16, k);
#pragma unroll
            for (int i = 0; i < 4; ++i) {
                int idx = tid + i * 256;
                rb[i] = ldB(t + 1, idx >> 6, idx & 63);
            }
        }
        int buf = t & 1;
#pragma unroll
        for (int k = 0; k < 16; ++k) {
            float a0 = As[buf][k][ty * 2];
            float a1 = As[buf][k][ty * 2 + 1];
            float b[4];
            *(float4*)b = *(const float4*)&Bs[buf][k][tx * 4];
#pragma unroll
            for (int j = 0; j < 4; ++j) {
                acc[0][j] = fmaf(a0, b[j], acc[0][j]);
                acc[1][j] = fmaf(a1, b[j], acc[1][j]);
            }
        }
        if (t + 1 < nkt) {
            int nb = buf ^ 1;
            int r = tid >> 4, k = tid & 15;
            As[nb][k][r] = ra0;
            As[nb][k][r + 16] = ra1;
#pragma unroll
            for (int i = 0; i < 4; ++i) {
                int idx = tid + i * 256;
                Bs[nb][idx >> 6][idx & 63] = rb[i];
            }
            __syncthreads();
        }
    }
}

// ---------------------------------------------------------------------------
// P0: H1 = relu(obs @ We1 + be1). grid (32,4) = 128 blocks. Zeroes sums.
// ---------------------------------------------------------------------------
__global__ void __launch_bounds__(256)
h1_kernel(const float* __restrict__ x, const float* __restrict__ We1,
          const float* __restrict__ be1)
{
    if (blockIdx.x == 0 && blockIdx.y == 0) {
        for (int i = threadIdx.x; i < BB * TT; i += 256) {
            g_sumNH[i] = 0.f;
            g_sumHID[i] = 0.f;
        }
    }
    __shared__ float As[2][16][33];
    __shared__ float Bs[2][16][68];
    const int r0 = blockIdx.x * 32;
    const int c0 = blockIdx.y * 64;
    const int tid = threadIdx.x, ty = tid >> 4, tx = tid & 15;

    float acc[2][4] = {};
    mm32x64(
        [&](int kt, int r, int k) {
            int kg = kt * 16 + k;
            int row = r0 + r, b = row >> 8, n = row & 255;
            return (kg < OBSD) ? x[b * ((NN + 1) * OBSD) + n * OBSD + kg] : 0.f;
        },
        [&](int kt, int kk, int c) {
            int kg = kt * 16 + kk;
            return (kg < OBSD) ? We1[kg * TT + c0 + c] : 0.f;
        },
        3, acc, tid, As, Bs);

#pragma unroll
    for (int i = 0; i < 2; ++i)
#pragma unroll
        for (int j = 0; j < 4; ++j) {
            int c = c0 + tx * 4 + j;
            g_H1[(r0 + ty * 2 + i) * TT + c] = fmaxf(acc[i][j] + be1[c], 0.f);
        }
}

// ---------------------------------------------------------------------------
// P1: EMBp[s] = H1 @ We2 over K-half s. grid (32,4,2) = 256 blocks.
// ---------------------------------------------------------------------------
__global__ void __launch_bounds__(256)
emb_kernel(const float* __restrict__ We2)
{
    __shared__ float As[2][16][33];
    __shared__ float Bs[2][16][68];
    const int r0 = blockIdx.x * 32;
    const int c0 = blockIdx.y * 64;
    const int kb = blockIdx.z * 128;
    const int tid = threadIdx.x, ty = tid >> 4, tx = tid & 15;

    float acc[2][4] = {};
    mm32x64(
        [&](int kt, int r, int k) { return g_H1[(r0 + r) * TT + kb + kt * 16 + k]; },
        [&](int kt, int kk, int c) { return We2[(kb + kt * 16 + kk) * TT + c0 + c]; },
        8, acc, tid, As, Bs);

    float* C = &g_EMBp[blockIdx.z][0];
#pragma unroll
    for (int i = 0; i < 2; ++i)
#pragma unroll
        for (int j = 0; j < 4; ++j)
            C[(r0 + ty * 2 + i) * TT + c0 + tx * 4 + j] = acc[i][j];
}

// ---------------------------------------------------------------------------
// P2: NEp[s][b] = adj @ EMB[b] over K-half s; EMB = relu(p0+p1+be2) on load.
// grid (8,4,8) = 256 blocks, z = b*2+s.
// ---------------------------------------------------------------------------
__global__ void __launch_bounds__(256)
ne_kernel(const float* __restrict__ adj, const float* __restrict__ be2)
{
    __shared__ float As[2][16][33];
    __shared__ float Bs[2][16][68];
    const int b = blockIdx.z >> 1;
    const int s = blockIdx.z & 1;
    const int kb = s * 128;
    const int r0 = blockIdx.x * 32;
    const int c0 = blockIdx.y * 64;
    const int ebase = b * (NN * TT);
    const int tid = threadIdx.x, ty = tid >> 4, tx = tid & 15;

    float acc[2][4] = {};
    mm32x64(
        [&](int kt, int r, int k) { return adj[(r0 + r) * NN + kb + kt * 16 + k]; },
        [&](int kt, int kk, int c) {
            int col = c0 + c;
            int ei = ebase + (kb + kt * 16 + kk) * TT + col;
            return fmaxf(g_EMBp[0][ei] + g_EMBp[1][ei] + be2[col], 0.f);
        },
        8, acc, tid, As, Bs);

    float* C = &g_NEp[s][ebase];
#pragma unroll
    for (int i = 0; i < 2; ++i)
#pragma unroll
        for (int j = 0; j < 4; ++j)
            C[(r0 + ty * 2 + i) * TT + c0 + tx * 4 + j] = acc[i][j];
}

// ---------------------------------------------------------------------------
// P3: colsum over rows of relu(NE @ {Wn|Wh} + bias); NE = p0+p1 on load.
// grid (8,8,4) = 256 blocks: x=row chunk(32), y= coltile|weight, z=batch.
// ---------------------------------------------------------------------------
__global__ void __launch_bounds__(256)
colsum_kernel(const float* __restrict__ Wn, const float* __restrict__ bn,
              const float* __restrict__ Wh, const float* __restrict__ bh)
{
    __shared__ float As[2][16][33];
    __shared__ float Bs[2][16][68];
    const int b = blockIdx.z;
    const int ct = blockIdx.y & 3;
    const int w = blockIdx.y >> 2;
    const int r0 = blockIdx.x * 32;
    const int c0 = ct * 64;
    const int abase = b * (NN * TT);
    const float* W = (w ? Wh : Wn) + c0;
    const int tid = threadIdx.x, ty = tid >> 4, tx = tid & 15;

    float acc[2][4] = {};
    mm32x64(
        [&](int kt, int r, int k) {
            int ai = abase + (r0 + r) * TT + kt * 16 + k;
            return g_NEp[0][ai] + g_NEp[1][ai];
        },
        [&](int kt, int kk, int c) { return W[(kt * 16 + kk) * TT + c]; },
        16, acc, tid, As, Bs);

    const float* bi = (w ? bh : bn);
    float* dst = (w ? g_sumHID : g_sumNH);
    float* red = &As[0][0][0];   // >= 1024 floats of smem
    __syncthreads();
#pragma unroll
    for (int j = 0; j < 4; ++j) {
        int col = tx * 4 + j;
        float bv = bi[c0 + col];
        red[ty * 64 + col] = fmaxf(acc[0][j] + bv, 0.f) + fmaxf(acc[1][j] + bv, 0.f);
    }
    __syncthreads();
    if (tid < 64) {
        float s = 0.f;
#pragma unroll
        for (int t2 = 0; t2 < 16; ++t2) s += red[t2 * 64 + tid];
        atomicAdd(&dst[b * TT + c0 + tid], s);
    }
}

// ---------------------------------------------------------------------------
// P4: epilogue per batch.
// ---------------------------------------------------------------------------
__global__ void __launch_bounds__(256)
final_kernel(const float* __restrict__ x, const float* __restrict__ be2,
             const float* __restrict__ Wl, const float* __restrict__ bl,
             const float* __restrict__ Wa, const float* __restrict__ ba,
             float* __restrict__ out)
{
    __shared__ float er[256];
    __shared__ float av[256];
    __shared__ float prod[256];
    __shared__ float mx[8], sm[8];
    __shared__ float od[32];

    const int b = blockIdx.x;
    const int t = threadIdx.x;

    const int tgt = (int)x[b * ((NN + 1) * OBSD) + NN * OBSD];
    int ei = (b * NN + tgt) * TT + t;
    er[t] = fmaxf(g_EMBp[0][ei] + g_EMBp[1][ei] + be2[t], 0.f);
    __syncthreads();

    float acc = bl[t];
#pragma unroll 8
    for (int k = 0; k < TT; ++k) acc = fmaf(er[k], Wl[k * TT + t], acc);
    float l = fmaxf(acc, 0.f);
    av[t] = l * g_sumNH[b * TT + t];
    __syncthreads();

    if (t < HEADG) {
        float m = -1e30f;
        for (int d = 0; d < DIMG; ++d) m = fmaxf(m, av[d * HEADG + t]);
        float s = 0.f;
        for (int d = 0; d < DIMG; ++d) s += __expf(av[d * HEADG + t] - m);
        mx[t] = m; sm[t] = s;
    }
    __syncthreads();

    int h = t & (HEADG - 1);
    float attn = __expf(av[t] - mx[h]) / sm[h];
    prod[t] = attn * g_sumHID[b * TT + t];
    __syncthreads();

    if (t < DIMG) {
        float s = 0.f;
#pragma unroll
        for (int hh = 0; hh < HEADG; ++hh) s += prod[t * HEADG + hh];
        od[t] = s * (1.0f / HEADG);
    }
    __syncthreads();

    if (t < ACTD) {
        float a = ba[t];
#pragma unroll
        for (int d = 0; d < DIMG; ++d) a = fmaf(od[d], Wa[d * ACTD + t], a);
        out[b * ACTD + t] = a;
    }
}

// ---------------------------------------------------------------------------
extern "C" void kernel_launch(void* const* d_in, const int* in_sizes, int n_in,
                              void* d_out, int out_size)
{
    const float* x   = (const float*)d_in[0];
    const float* adj = (const float*)d_in[1];
    const float* We1 = (const float*)d_in[2];
    const float* be1 = (const float*)d_in[3];
    const float* We2 = (const float*)d_in[4];
    const float* be2 = (const float*)d_in[5];
    const float* Wl  = (const float*)d_in[6];
    const float* bl  = (const float*)d_in[7];
    const float* Wn  = (const float*)d_in[8];
    const float* bn  = (const float*)d_in[9];
    const float* Wh  = (const float*)d_in[10];
    const float* bh  = (const float*)d_in[11];
    const float* Wa  = (const float*)d_in[12];
    const float* ba  = (const float*)d_in[13];
    float* out = (float*)d_out;

    h1_kernel<<<dim3(32, 4), 256>>>(x, We1, be1);
    emb_kernel<<<dim3(32, 4, 2), 256>>>(We2);
    ne_kernel<<<dim3(8, 4, 8), 256>>>(adj, be2);
    colsum_kernel<<<dim3(8, 8, 4), 256>>>(Wn, bn, Wh, bh);
    final_kernel<<<BB, 256>>>(x, be2, Wl, bl, Wa, ba, out);
}

// round 6
// speedup vs baseline: 1.9765x; 1.1667x over previous
#include <cuda_runtime.h>

#define BB   4
#define NN   256
#define OBSD 40
#define TT   256
#define DIMG 32
#define HEADG 8
#define ACTD 8

__device__ float g_H1[BB * NN * TT];
__device__ float g_EMBp[2][BB * NN * TT];
__device__ float g_NEp[2][BB * NN * TT];
__device__ float g_sumNH[BB * TT];
__device__ float g_sumHID[BB * TT];

// ---------------------------------------------------------------------------
// 32x64 output tile, 128 threads (8x16), 4x4 micro-tile, double-buffered
// k-tiles of 16. ldA(kt,r,k): A[row r(0..31)][k] of tile kt; ldB(kt,kk,c).
// ---------------------------------------------------------------------------
template <class FA, class FB>
__device__ __forceinline__ void mm32x64(FA ldA, FB ldB, int nkt,
                                        float acc[4][4], int tid,
                                        float As[2][16][36], float Bs[2][16][68])
{
    const int ty = tid >> 4, tx = tid & 15;
    {
#pragma unroll
        for (int i = 0; i < 4; ++i) {
            int idx = tid + i * 128;
            As[0][idx & 15][idx >> 4] = ldA(0, idx >> 4, idx & 15);
        }
#pragma unroll
        for (int i = 0; i < 8; ++i) {
            int idx = tid + i * 128;
            Bs[0][idx >> 6][idx & 63] = ldB(0, idx >> 6, idx & 63);
        }
    }
    __syncthreads();
    for (int t = 0; t < nkt; ++t) {
        float ra[4], rb[8];
        if (t + 1 < nkt) {
#pragma unroll
            for (int i = 0; i < 4; ++i) {
                int idx = tid + i * 128;
                ra[i] = ldA(t + 1, idx >> 4, idx & 15);
            }
#pragma unroll
            for (int i = 0; i < 8; ++i) {
                int idx = tid + i * 128;
                rb[i] = ldB(t + 1, idx >> 6, idx & 63);
            }
        }
        int buf = t & 1;
#pragma unroll
        for (int k = 0; k < 16; ++k) {
            float a[4], b[4];
            *(float4*)a = *(const float4*)&As[buf][k][ty * 4];
            *(float4*)b = *(const float4*)&Bs[buf][k][tx * 4];
#pragma unroll
            for (int i = 0; i < 4; ++i)
#pragma unroll
                for (int j = 0; j < 4; ++j) acc[i][j] = fmaf(a[i], b[j], acc[i][j]);
        }
        if (t + 1 < nkt) {
            int nb = buf ^ 1;
#pragma unroll
            for (int i = 0; i < 4; ++i) {
                int idx = tid + i * 128;
                As[nb][idx & 15][idx >> 4] = ra[i];
            }
#pragma unroll
            for (int i = 0; i < 8; ++i) {
                int idx = tid + i * 128;
                Bs[nb][idx >> 6][idx & 63] = rb[i];
            }
            __syncthreads();
        }
    }
}

// ---------------------------------------------------------------------------
// P0: H1 = relu(obs @ We1 + be1). grid (32,4) = 128 blocks. Zeroes sums.
// ---------------------------------------------------------------------------
__global__ void __launch_bounds__(128)
h1_kernel(const float* __restrict__ x, const float* __restrict__ We1,
          const float* __restrict__ be1)
{
    if (blockIdx.x == 0 && blockIdx.y == 0) {
        for (int i = threadIdx.x; i < BB * TT; i += 128) {
            g_sumNH[i] = 0.f;
            g_sumHID[i] = 0.f;
        }
    }
    __shared__ float As[2][16][36];
    __shared__ float Bs[2][16][68];
    const int r0 = blockIdx.x * 32;
    const int c0 = blockIdx.y * 64;
    const int tid = threadIdx.x, ty = tid >> 4, tx = tid & 15;

    float acc[4][4] = {};
    mm32x64(
        [&](int kt, int r, int k) {
            int kg = kt * 16 + k;
            int row = r0 + r, b = row >> 8, n = row & 255;
            return (kg < OBSD) ? x[b * ((NN + 1) * OBSD) + n * OBSD + kg] : 0.f;
        },
        [&](int kt, int kk, int c) {
            int kg = kt * 16 + kk;
            return (kg < OBSD) ? We1[kg * TT + c0 + c] : 0.f;
        },
        3, acc, tid, As, Bs);

#pragma unroll
    for (int i = 0; i < 4; ++i)
#pragma unroll
        for (int j = 0; j < 4; ++j) {
            int c = c0 + tx * 4 + j;
            g_H1[(r0 + ty * 4 + i) * TT + c] = fmaxf(acc[i][j] + be1[c], 0.f);
        }
}

// ---------------------------------------------------------------------------
// P1: EMBp[s] = H1 @ We2 over K-half s. grid (32,4,2) = 256 blocks.
// ---------------------------------------------------------------------------
__global__ void __launch_bounds__(128)
emb_kernel(const float* __restrict__ We2)
{
    __shared__ float As[2][16][36];
    __shared__ float Bs[2][16][68];
    const int r0 = blockIdx.x * 32;
    const int c0 = blockIdx.y * 64;
    const int kb = blockIdx.z * 128;
    const int tid = threadIdx.x, ty = tid >> 4, tx = tid & 15;

    float acc[4][4] = {};
    mm32x64(
        [&](int kt, int r, int k) { return g_H1[(r0 + r) * TT + kb + kt * 16 + k]; },
        [&](int kt, int kk, int c) { return We2[(kb + kt * 16 + kk) * TT + c0 + c]; },
        8, acc, tid, As, Bs);

    float* C = &g_EMBp[blockIdx.z][0];
#pragma unroll
    for (int i = 0; i < 4; ++i)
#pragma unroll
        for (int j = 0; j < 4; ++j)
            C[(r0 + ty * 4 + i) * TT + c0 + tx * 4 + j] = acc[i][j];
}

// ---------------------------------------------------------------------------
// P2: NEp[s][b] = adj @ EMB[b] over K-half s; EMB = relu(p0+p1+be2) on load.
// grid (8,4,8) = 256 blocks, z = b*2+s.
// ---------------------------------------------------------------------------
__global__ void __launch_bounds__(128)
ne_kernel(const float* __restrict__ adj, const float* __restrict__ be2)
{
    __shared__ float As[2][16][36];
    __shared__ float Bs[2][16][68];
    const int b = blockIdx.z >> 1;
    const int s = blockIdx.z & 1;
    const int kb = s * 128;
    const int r0 = blockIdx.x * 32;
    const int c0 = blockIdx.y * 64;
    const int ebase = b * (NN * TT);
    const int tid = threadIdx.x, ty = tid >> 4, tx = tid & 15;

    float acc[4][4] = {};
    mm32x64(
        [&](int kt, int r, int k) { return adj[(r0 + r) * NN + kb + kt * 16 + k]; },
        [&](int kt, int kk, int c) {
            int col = c0 + c;
            int ei = ebase + (kb + kt * 16 + kk) * TT + col;
            return fmaxf(g_EMBp[0][ei] + g_EMBp[1][ei] + be2[col], 0.f);
        },
        8, acc, tid, As, Bs);

    float* C = &g_NEp[s][ebase];
#pragma unroll
    for (int i = 0; i < 4; ++i)
#pragma unroll
        for (int j = 0; j < 4; ++j)
            C[(r0 + ty * 4 + i) * TT + c0 + tx * 4 + j] = acc[i][j];
}

// ---------------------------------------------------------------------------
// P3: colsum over rows of relu(NE @ {Wn|Wh} + bias); NE = p0+p1 on load.
// grid (8,8,4) = 256 blocks.
// ---------------------------------------------------------------------------
__global__ void __launch_bounds__(128)
colsum_kernel(const float* __restrict__ Wn, const float* __restrict__ bn,
              const float* __restrict__ Wh, const float* __restrict__ bh)
{
    __shared__ float As[2][16][36];
    __shared__ float Bs[2][16][68];
    const int b = blockIdx.z;
    const int ct = blockIdx.y & 3;
    const int w = blockIdx.y >> 2;
    const int r0 = blockIdx.x * 32;
    const int c0 = ct * 64;
    const int abase = b * (NN * TT);
    const float* W = (w ? Wh : Wn) + c0;
    const int tid = threadIdx.x, ty = tid >> 4, tx = tid & 15;

    float acc[4][4] = {};
    mm32x64(
        [&](int kt, int r, int k) {
            int ai = abase + (r0 + r) * TT + kt * 16 + k;
            return g_NEp[0][ai] + g_NEp[1][ai];
        },
        [&](int kt, int kk, int c) { return W[(kt * 16 + kk) * TT + c]; },
        16, acc, tid, As, Bs);

    const float* bi = (w ? bh : bn);
    float* dst = (w ? g_sumHID : g_sumNH);
    float* red = &As[0][0][0];   // 8*64 floats
    __syncthreads();
#pragma unroll
    for (int j = 0; j < 4; ++j) {
        int col = tx * 4 + j;
        float bv = bi[c0 + col];
        float s = 0.f;
#pragma unroll
        for (int i = 0; i < 4; ++i) s += fmaxf(acc[i][j] + bv, 0.f);
        red[ty * 64 + col] = s;
    }
    __syncthreads();
    if (tid < 64) {
        float s = 0.f;
#pragma unroll
        for (int t2 = 0; t2 < 8; ++t2) s += red[t2 * 64 + tid];
        atomicAdd(&dst[b * TT + c0 + tid], s);
    }
}

// ---------------------------------------------------------------------------
// P4: epilogue per batch.
// ---------------------------------------------------------------------------
__global__ void __launch_bounds__(256)
final_kernel(const float* __restrict__ x, const float* __restrict__ be2,
             const float* __restrict__ Wl, const float* __restrict__ bl,
             const float* __restrict__ Wa, const float* __restrict__ ba,
             float* __restrict__ out)
{
    __shared__ float er[256];
    __shared__ float av[256];
    __shared__ float prod[256];
    __shared__ float mx[8], sm[8];
    __shared__ float od[32];

    const int b = blockIdx.x;
    const int t = threadIdx.x;

    const int tgt = (int)x[b * ((NN + 1) * OBSD) + NN * OBSD];
    int ei = (b * NN + tgt) * TT + t;
    er[t] = fmaxf(g_EMBp[0][ei] + g_EMBp[1][ei] + be2[t], 0.f);
    __syncthreads();

    float acc = bl[t];
#pragma unroll 8
    for (int k = 0; k < TT; ++k) acc = fmaf(er[k], Wl[k * TT + t], acc);
    float l = fmaxf(acc, 0.f);
    av[t] = l * g_sumNH[b * TT + t];
    __syncthreads();

    if (t < HEADG) {
        float m = -1e30f;
        for (int d = 0; d < DIMG; ++d) m = fmaxf(m, av[d * HEADG + t]);
        float s = 0.f;
        for (int d = 0; d < DIMG; ++d) s += __expf(av[d * HEADG + t] - m);
        mx[t] = m; sm[t] = s;
    }
    __syncthreads();

    int h = t & (HEADG - 1);
    float attn = __expf(av[t] - mx[h]) / sm[h];
    prod[t] = attn * g_sumHID[b * TT + t];
    __syncthreads();

    if (t < DIMG) {
        float s = 0.f;
#pragma unroll
        for (int hh = 0; hh < HEADG; ++hh) s += prod[t * HEADG + hh];
        od[t] = s * (1.0f / HEADG);
    }
    __syncthreads();

    if (t < ACTD) {
        float a = ba[t];
#pragma unroll
        for (int d = 0; d < DIMG; ++d) a = fmaf(od[d], Wa[d * ACTD + t], a);
        out[b * ACTD + t] = a;
    }
}

// ---------------------------------------------------------------------------
extern "C" void kernel_launch(void* const* d_in, const int* in_sizes, int n_in,
                              void* d_out, int out_size)
{
    const float* x   = (const float*)d_in[0];
    const float* adj = (const float*)d_in[1];
    const float* We1 = (const float*)d_in[2];
    const float* be1 = (const float*)d_in[3];
    const float* We2 = (const float*)d_in[4];
    const float* be2 = (const float*)d_in[5];
    const float* Wl  = (const float*)d_in[6];
    const float* bl  = (const float*)d_in[7];
    const float* Wn  = (const float*)d_in[8];
    const float* bn  = (const float*)d_in[9];
    const float* Wh  = (const float*)d_in[10];
    const float* bh  = (const float*)d_in[11];
    const float* Wa  = (const float*)d_in[12];
    const float* ba  = (const float*)d_in[13];
    float* out = (float*)d_out;

    h1_kernel<<<dim3(32, 4), 128>>>(x, We1, be1);
    emb_kernel<<<dim3(32, 4, 2), 128>>>(We2);
    ne_kernel<<<dim3(8, 4, 8), 128>>>(adj, be2);
    colsum_kernel<<<dim3(8, 8, 4), 128>>>(Wn, bn, Wh, bh);
    final_kernel<<<BB, 256>>>(x, be2, Wl, bl, Wa, ba, out);
}